// round 3
// baseline (speedup 1.0000x reference)
#include <cuda_runtime.h>
#include <cuda_bf16.h>
#include <cstdint>
#include <cstddef>

// ---------------------------------------------------------------------------
// Problem dims
// ---------------------------------------------------------------------------
#define M_DIM 8192
#define N_DIM 4096
#define K_DIM 4096

// GEMM tiling (int8)
#define BM 128
#define BN 128
#define BK 128                   // int8 elems per K-tile = 128 bytes/row
#define STAGES 3
#define KT (K_DIM / BK)          // 32
#define GEMM_THREADS 256         // 8 warps: 2 (M) x 4 (N), warp tile 64x32

#define A_TILE_BYTES (BM * 128)                        // 16 KB (one of hi/lo)
#define B_TILE_BYTES (BN * 128)                        // 16 KB
#define STAGE_BYTES  (2 * A_TILE_BYTES + B_TILE_BYTES) // 48 KB
#define SMEM_TOTAL   (STAGES * STAGE_BYTES)            // 144 KB

#define QMAX 16256               // 127 * 128 : 15-bit fixed-point range

// ---------------------------------------------------------------------------
// Device scratch (allocation-free rule: __device__ globals)
// ---------------------------------------------------------------------------
__device__ float g_partials[1024];
__device__ float g_thr;
__device__ __align__(1024) int8_t g_q   [(size_t)N_DIM * K_DIM]; // 16 MB {-1,0,1}
__device__ __align__(1024) int8_t g_xhi [(size_t)M_DIM * K_DIM]; // 32 MB hi limb
__device__ __align__(1024) int8_t g_xlo [(size_t)M_DIM * K_DIM]; // 32 MB lo limb
__device__ float g_rowscale[M_DIM];                              // s_row
__device__ float g_rowinv  [M_DIM];                              // 1/s_row

// ---------------------------------------------------------------------------
// Helpers
// ---------------------------------------------------------------------------
__device__ __forceinline__ uint32_t smem_u32(const void* p) {
    return (uint32_t)__cvta_generic_to_shared(p);
}

__device__ __forceinline__ void cp16(uint32_t dst, const void* src) {
    asm volatile("cp.async.cg.shared.global [%0], [%1], 16;" :: "r"(dst), "l"(src));
}

__device__ __forceinline__ void ldsm_x4(uint32_t (&r)[4], uint32_t addr) {
    asm volatile("ldmatrix.sync.aligned.m8n8.x4.shared.b16 {%0,%1,%2,%3}, [%4];"
                 : "=r"(r[0]), "=r"(r[1]), "=r"(r[2]), "=r"(r[3]) : "r"(addr));
}

__device__ __forceinline__ void imma16832(int (&c)[4], const uint32_t (&a)[4],
                                          uint32_t b0, uint32_t b1) {
    asm volatile(
        "mma.sync.aligned.m16n8k32.row.col.s32.s8.s8.s32 "
        "{%0,%1,%2,%3}, {%4,%5,%6,%7}, {%8,%9}, {%0,%1,%2,%3};"
        : "+r"(c[0]), "+r"(c[1]), "+r"(c[2]), "+r"(c[3])
        : "r"(a[0]), "r"(a[1]), "r"(a[2]), "r"(a[3]), "r"(b0), "r"(b1));
}

__device__ __forceinline__ uint32_t pack4s8(int a, int b, int c, int d) {
    return (uint32_t)(a & 0xFF) | ((uint32_t)(b & 0xFF) << 8) |
           ((uint32_t)(c & 0xFF) << 16) | ((uint32_t)(d & 0xFF) << 24);
}

// ---------------------------------------------------------------------------
// Prep: threshold reduction
// ---------------------------------------------------------------------------
__global__ void k_abs_partial(const float* __restrict__ w) {
    const float4* w4 = (const float4*)w;
    const int n4 = (N_DIM * K_DIM) / 4;
    float s = 0.0f;
    for (int i = blockIdx.x * blockDim.x + threadIdx.x; i < n4; i += gridDim.x * blockDim.x) {
        float4 v = w4[i];
        s += fabsf(v.x) + fabsf(v.y) + fabsf(v.z) + fabsf(v.w);
    }
    __shared__ float sm[256];
    sm[threadIdx.x] = s;
    __syncthreads();
    for (int o = 128; o > 0; o >>= 1) {
        if (threadIdx.x < o) sm[threadIdx.x] += sm[threadIdx.x + o];
        __syncthreads();
    }
    if (threadIdx.x == 0) g_partials[blockIdx.x] = sm[0];
}

__global__ void k_thr() {
    __shared__ float sm[1024];
    sm[threadIdx.x] = g_partials[threadIdx.x];
    __syncthreads();
    for (int o = 512; o > 0; o >>= 1) {
        if (threadIdx.x < o) sm[threadIdx.x] += sm[threadIdx.x + o];
        __syncthreads();
    }
    if (threadIdx.x == 0)
        g_thr = 0.05f * (sm[0] / (float)((size_t)N_DIM * K_DIM));
}

// Ternary quantize w -> s8 {-1,0,1}
__global__ void k_quant(const float* __restrict__ w) {
    const float thr = g_thr;
    const float4* w4 = (const float4*)w;
    uint32_t* q4 = (uint32_t*)g_q;
    const int n4 = (N_DIM * K_DIM) / 4;
    for (int i = blockIdx.x * blockDim.x + threadIdx.x; i < n4; i += gridDim.x * blockDim.x) {
        float4 v = w4[i];
        int q0 = (v.x > thr) ? 1 : ((v.x < -thr) ? -1 : 0);
        int q1 = (v.y > thr) ? 1 : ((v.y < -thr) ? -1 : 0);
        int q2 = (v.z > thr) ? 1 : ((v.z < -thr) ? -1 : 0);
        int q3 = (v.w > thr) ? 1 : ((v.w < -thr) ? -1 : 0);
        q4[i] = pack4s8(q0, q1, q2, q3);
    }
}

// Per-row max|x| -> scale
__global__ void k_rowmax(const float* __restrict__ x) {
    const int row = blockIdx.x;
    const float4* x4 = (const float4*)(x + (size_t)row * K_DIM);
    float mx = 0.0f;
    for (int i = threadIdx.x; i < K_DIM / 4; i += blockDim.x) {
        float4 v = x4[i];
        mx = fmaxf(mx, fmaxf(fmaxf(fabsf(v.x), fabsf(v.y)), fmaxf(fabsf(v.z), fabsf(v.w))));
    }
    __shared__ float sm[128];
    sm[threadIdx.x] = mx;
    __syncthreads();
    for (int o = 64; o > 0; o >>= 1) {
        if (threadIdx.x < o) sm[threadIdx.x] = fmaxf(sm[threadIdx.x], sm[threadIdx.x + o]);
        __syncthreads();
    }
    if (threadIdx.x == 0) {
        float m = fmaxf(sm[0], 1e-30f);
        g_rowscale[row] = m / (float)QMAX;
        g_rowinv[row]   = (float)QMAX / m;
    }
}

// x -> two s8 limbs: x ~= s_row * (128*hi + lo)
__global__ void k_xquant(const float* __restrict__ x) {
    const float4* x4 = (const float4*)x;
    uint32_t* hi4 = (uint32_t*)g_xhi;
    uint32_t* lo4 = (uint32_t*)g_xlo;
    const int n4 = (M_DIM * K_DIM) / 4;
    for (int i = blockIdx.x * blockDim.x + threadIdx.x; i < n4; i += gridDim.x * blockDim.x) {
        const int row = (i * 4) >> 12;   // K_DIM = 4096
        const float inv = g_rowinv[row];
        float4 v = x4[i];
        int h[4], l[4];
        float vv[4] = {v.x, v.y, v.z, v.w};
        #pragma unroll
        for (int j = 0; j < 4; j++) {
            int q = __float2int_rn(vv[j] * inv);
            q = max(-QMAX, min(QMAX, q));
            int ah = (q + 64) >> 7;            // round((q)/128), ah in [-127,127]
            int al = q - (ah << 7);            // in [-64, 64)
            h[j] = ah; l[j] = al;
        }
        hi4[i] = pack4s8(h[0], h[1], h[2], h[3]);
        lo4[i] = pack4s8(l[0], l[1], l[2], l[3]);
    }
}

// ---------------------------------------------------------------------------
// GEMM: acc_hi = xhi @ q^T, acc_lo = xlo @ q^T  via mma m16n8k32 s8 (int32 acc)
//   out = s_row * (128*acc_hi + acc_lo). B tile shared by both passes.
// ---------------------------------------------------------------------------
__global__ void __launch_bounds__(GEMM_THREADS, 1)
k_gemm(float* __restrict__ out) {
    extern __shared__ char smem[];
    const uint32_t sb = smem_u32(smem);
    const int tid  = threadIdx.x;
    const int wid  = tid >> 5;
    const int lane = tid & 31;
    const int warp_m = wid & 1;   // 64 rows each
    const int warp_n = wid >> 1;  // 32 cols each
    const int m0 = blockIdx.y * BM;
    const int n0 = blockIdx.x * BN;

    // ---- async tile loader (XOR-swizzled 16B chunks, 128B rows) ----
    auto load_stage = [&](int kt, int st) {
        const uint32_t base = sb + st * STAGE_BYTES;
        const size_t kofs = (size_t)kt * BK;
        #pragma unroll
        for (int i = tid; i < BM * 8; i += GEMM_THREADS) {
            const int r = i >> 3, c = i & 7;
            const uint32_t d = base + r * 128 + ((c ^ (r & 7)) << 4);
            const size_t g = (size_t)(m0 + r) * K_DIM + kofs + c * 16;
            cp16(d, &g_xhi[g]);
            cp16(d + A_TILE_BYTES, &g_xlo[g]);
        }
        #pragma unroll
        for (int i = tid; i < BN * 8; i += GEMM_THREADS) {
            const int r = i >> 3, c = i & 7;
            const uint32_t d = base + 2 * A_TILE_BYTES + r * 128 + ((c ^ (r & 7)) << 4);
            cp16(d, &g_q[(size_t)(n0 + r) * K_DIM + kofs + c * 16]);
        }
        asm volatile("cp.async.commit_group;" ::: "memory");
    };

    int acch[4][4][4], accl[4][4][4];
    #pragma unroll
    for (int mi = 0; mi < 4; mi++)
        #pragma unroll
        for (int ni = 0; ni < 4; ni++)
            #pragma unroll
            for (int j = 0; j < 4; j++) { acch[mi][ni][j] = 0; accl[mi][ni][j] = 0; }

    // ldmatrix lane addressing:
    // A: lanes 0-15 -> rows base+0..15 (chunk lo), lanes 16-31 -> same rows (chunk hi)
    const int a_row  = warp_m * 64 + (lane & 15);
    const int lhalf  = lane >> 4;                     // chunk +0 / +1
    // B: same pattern over 16 n-rows per ldsm.x4 (covers 2 n8-tiles)
    const int b_rowb = warp_n * 32 + (lane & 15);

    #pragma unroll
    for (int j = 0; j < STAGES - 1; j++) load_stage(j, j);

    for (int it = 0; it < KT; it++) {
        const int st = it % STAGES;
        asm volatile("cp.async.wait_group %0;" :: "n"(STAGES - 2) : "memory");
        __syncthreads();

        const uint32_t abase_hi = sb + st * STAGE_BYTES;
        const uint32_t abase_lo = abase_hi + A_TILE_BYTES;
        const uint32_t bbase    = abase_hi + 2 * A_TILE_BYTES;

        #pragma unroll
        for (int ks = 0; ks < 4; ks++) {  // 4 x k32 covers BK=128
            const int ch = ks * 2 + lhalf;
            // B frags: 2 ldsm.x4 -> 4 n8-frags (reg pairs {r0,r2},{r1,r3})
            uint32_t bfr[4][2];
            #pragma unroll
            for (int jt = 0; jt < 2; jt++) {
                const int n = b_rowb + jt * 16;
                uint32_t r4[4];
                ldsm_x4(r4, bbase + n * 128 + ((ch ^ (n & 7)) << 4));
                bfr[2 * jt + 0][0] = r4[0]; bfr[2 * jt + 0][1] = r4[2];
                bfr[2 * jt + 1][0] = r4[1]; bfr[2 * jt + 1][1] = r4[3];
            }
            // hi pass
            #pragma unroll
            for (int mi = 0; mi < 4; mi++) {
                const int r = a_row + mi * 16;
                uint32_t a4[4];
                ldsm_x4(a4, abase_hi + r * 128 + ((ch ^ (r & 7)) << 4));
                #pragma unroll
                for (int ni = 0; ni < 4; ni++)
                    imma16832(acch[mi][ni], a4, bfr[ni][0], bfr[ni][1]);
            }
            // lo pass (same B frags)
            #pragma unroll
            for (int mi = 0; mi < 4; mi++) {
                const int r = a_row + mi * 16;
                uint32_t a4[4];
                ldsm_x4(a4, abase_lo + r * 128 + ((ch ^ (r & 7)) << 4));
                #pragma unroll
                for (int ni = 0; ni < 4; ni++)
                    imma16832(accl[mi][ni], a4, bfr[ni][0], bfr[ni][1]);
            }
        }

        if (it + STAGES - 1 < KT) load_stage(it + STAGES - 1, (it + STAGES - 1) % STAGES);
        else asm volatile("cp.async.commit_group;" ::: "memory");
    }

    // ---- epilogue: combine limbs, scale per row, float2 stores ----
    const int er = lane >> 2;
    const int ec = (lane & 3) * 2;
    #pragma unroll
    for (int mi = 0; mi < 4; mi++) {
        const int row0 = m0 + warp_m * 64 + mi * 16 + er;
        const float s0 = g_rowscale[row0];
        const float s1 = g_rowscale[row0 + 8];
        #pragma unroll
        for (int ni = 0; ni < 4; ni++) {
            const int col = n0 + warp_n * 32 + ni * 8 + ec;
            const int t0 = (acch[mi][ni][0] << 7) + accl[mi][ni][0];
            const int t1 = (acch[mi][ni][1] << 7) + accl[mi][ni][1];
            const int t2 = (acch[mi][ni][2] << 7) + accl[mi][ni][2];
            const int t3 = (acch[mi][ni][3] << 7) + accl[mi][ni][3];
            float2 v0 = make_float2(s0 * (float)t0, s0 * (float)t1);
            float2 v1 = make_float2(s1 * (float)t2, s1 * (float)t3);
            *(float2*)&out[(size_t)row0 * N_DIM + col] = v0;
            *(float2*)&out[(size_t)(row0 + 8) * N_DIM + col] = v1;
        }
    }
}

// ---------------------------------------------------------------------------
// Launch
// ---------------------------------------------------------------------------
extern "C" void kernel_launch(void* const* d_in, const int* in_sizes, int n_in,
                              void* d_out, int out_size) {
    const float* x = (const float*)d_in[0];   // [8192, 4096]
    const float* w = (const float*)d_in[1];   // [4096, 4096]
    float* out = (float*)d_out;               // [8192, 4096]

    cudaFuncSetAttribute(k_gemm, cudaFuncAttributeMaxDynamicSharedMemorySize, SMEM_TOTAL);

    k_abs_partial<<<1024, 256>>>(w);
    k_thr<<<1, 1024>>>();
    k_quant<<<4096, 256>>>(w);
    k_rowmax<<<M_DIM, 128>>>(x);
    k_xquant<<<8192, 256>>>(x);

    // N-blocks fast: a concurrent wave shares q (16 MB, L2-resident)
    dim3 grid(N_DIM / BN, M_DIM / BM);
    k_gemm<<<grid, GEMM_THREADS, SMEM_TOTAL>>>(out);
}

// round 4
// speedup vs baseline: 5.2572x; 5.2572x over previous
#include <cuda_runtime.h>
#include <cuda_fp16.h>
#include <cstdint>
#include <cstddef>

// ---------------------------------------------------------------------------
// Problem dims
// ---------------------------------------------------------------------------
#define M_DIM 8192
#define N_DIM 4096
#define K_DIM 4096

// GEMM tiling
#define BM 128
#define BN 128
#define BK 64                    // fp16 elems per K-tile = 128 bytes/row
#define STAGES 4
#define KT (K_DIM / BK)          // 64
#define GEMM_THREADS 256         // 8 warps: 2 (M) x 4 (N), warp tile 64x32

#define A_TILE_BYTES (BM * 128)                 // 16 KB
#define B_TILE_BYTES (BN * 128)                 // 16 KB
#define STAGE_BYTES  (A_TILE_BYTES + B_TILE_BYTES) // 32 KB
#define SMEM_TOTAL   (STAGES * STAGE_BYTES)        // 128 KB

// ---------------------------------------------------------------------------
// Device scratch (allocation-free rule: __device__ globals)
// ---------------------------------------------------------------------------
__device__ float g_partials[1024];
__device__ float g_thr;
__device__ __align__(1024) __half g_q [(size_t)N_DIM * K_DIM]; // 32 MB {-1,0,1} exact
__device__ __align__(1024) __half g_xh[(size_t)M_DIM * K_DIM]; // 64 MB x in fp16

// ---------------------------------------------------------------------------
// Helpers
// ---------------------------------------------------------------------------
__device__ __forceinline__ uint32_t smem_u32(const void* p) {
    return (uint32_t)__cvta_generic_to_shared(p);
}

__device__ __forceinline__ void cp16(uint32_t dst, const void* src) {
    asm volatile("cp.async.cg.shared.global [%0], [%1], 16;" :: "r"(dst), "l"(src));
}

__device__ __forceinline__ void ldsm_x4(uint32_t (&r)[4], uint32_t addr) {
    asm volatile("ldmatrix.sync.aligned.m8n8.x4.shared.b16 {%0,%1,%2,%3}, [%4];"
                 : "=r"(r[0]), "=r"(r[1]), "=r"(r[2]), "=r"(r[3]) : "r"(addr));
}

__device__ __forceinline__ void mma16816(float (&c)[4], const uint32_t (&a)[4],
                                         uint32_t b0, uint32_t b1) {
    asm volatile(
        "mma.sync.aligned.m16n8k16.row.col.f32.f16.f16.f32 "
        "{%0,%1,%2,%3}, {%4,%5,%6,%7}, {%8,%9}, {%0,%1,%2,%3};"
        : "+f"(c[0]), "+f"(c[1]), "+f"(c[2]), "+f"(c[3])
        : "r"(a[0]), "r"(a[1]), "r"(a[2]), "r"(a[3]), "r"(b0), "r"(b1));
}

__device__ __forceinline__ uint32_t pack2h(float a, float b) {
    __half2 t = __floats2half2_rn(a, b);
    union { __half2 h; uint32_t u; } cv;
    cv.h = t;
    return cv.u;
}

// ---------------------------------------------------------------------------
// Prep kernels
// ---------------------------------------------------------------------------
__global__ void k_abs_partial(const float* __restrict__ w) {
    const float4* w4 = (const float4*)w;
    const int n4 = (N_DIM * K_DIM) / 4;
    float s = 0.0f;
    for (int i = blockIdx.x * blockDim.x + threadIdx.x; i < n4; i += gridDim.x * blockDim.x) {
        float4 v = w4[i];
        s += fabsf(v.x) + fabsf(v.y) + fabsf(v.z) + fabsf(v.w);
    }
    __shared__ float sm[256];
    sm[threadIdx.x] = s;
    __syncthreads();
    for (int o = 128; o > 0; o >>= 1) {
        if (threadIdx.x < o) sm[threadIdx.x] += sm[threadIdx.x + o];
        __syncthreads();
    }
    if (threadIdx.x == 0) g_partials[blockIdx.x] = sm[0];
}

__global__ void k_thr() {
    __shared__ float sm[1024];
    sm[threadIdx.x] = g_partials[threadIdx.x];
    __syncthreads();
    for (int o = 512; o > 0; o >>= 1) {
        if (threadIdx.x < o) sm[threadIdx.x] += sm[threadIdx.x + o];
        __syncthreads();
    }
    if (threadIdx.x == 0)
        g_thr = 0.05f * (sm[0] / (float)((size_t)N_DIM * K_DIM));
}

__device__ __forceinline__ float tq(float v, float thr) {
    return v > thr ? 1.0f : (v < -thr ? -1.0f : 0.0f);
}

// w -> ternary fp16 (exact)
__global__ void k_quant(const float* __restrict__ w) {
    const float thr = g_thr;
    const float4* w4 = (const float4*)w;
    uint2* q4 = (uint2*)g_q;
    const int n4 = (N_DIM * K_DIM) / 4;
    for (int i = blockIdx.x * blockDim.x + threadIdx.x; i < n4; i += gridDim.x * blockDim.x) {
        float4 v = w4[i];
        uint2 o;
        o.x = pack2h(tq(v.x, thr), tq(v.y, thr));
        o.y = pack2h(tq(v.z, thr), tq(v.w, thr));
        q4[i] = o;
    }
}

// x -> fp16
__global__ void k_conv(const float* __restrict__ x) {
    const float4* x4 = (const float4*)x;
    uint2* h4 = (uint2*)g_xh;
    const int n4 = (M_DIM * K_DIM) / 4;
    for (int i = blockIdx.x * blockDim.x + threadIdx.x; i < n4; i += gridDim.x * blockDim.x) {
        float4 v = x4[i];
        uint2 o;
        o.x = pack2h(v.x, v.y);
        o.y = pack2h(v.z, v.w);
        h4[i] = o;
    }
}

// ---------------------------------------------------------------------------
// GEMM: out = x_fp16 @ q^T via mma.sync m16n8k16 f16 (fp32 accum), single pass
// ---------------------------------------------------------------------------
__global__ void __launch_bounds__(GEMM_THREADS, 1)
k_gemm(float* __restrict__ out) {
    extern __shared__ char smem[];
    const uint32_t sb = smem_u32(smem);
    const int tid  = threadIdx.x;
    const int wid  = tid >> 5;
    const int lane = tid & 31;
    const int warp_m = wid & 1;   // 64 rows each
    const int warp_n = wid >> 1;  // 32 cols each
    const int m0 = blockIdx.y * BM;
    const int n0 = blockIdx.x * BN;

    // ---- async tile loader (XOR-swizzled 16B chunks, 128B rows) ----
    auto load_stage = [&](int kt, int st) {
        const uint32_t base = sb + st * STAGE_BYTES;
        const size_t kofs = (size_t)kt * BK;
        #pragma unroll
        for (int i = tid; i < BM * 8; i += GEMM_THREADS) {
            const int r = i >> 3, c = i & 7;
            const uint32_t d = base + r * 128 + ((c ^ (r & 7)) << 4);
            cp16(d, &g_xh[(size_t)(m0 + r) * K_DIM + kofs + c * 8]);
        }
        #pragma unroll
        for (int i = tid; i < BN * 8; i += GEMM_THREADS) {
            const int r = i >> 3, c = i & 7;
            const uint32_t d = base + A_TILE_BYTES + r * 128 + ((c ^ (r & 7)) << 4);
            cp16(d, &g_q[(size_t)(n0 + r) * K_DIM + kofs + c * 8]);
        }
        asm volatile("cp.async.commit_group;" ::: "memory");
    };

    float acc[4][4][4];
    #pragma unroll
    for (int mi = 0; mi < 4; mi++)
        #pragma unroll
        for (int ni = 0; ni < 4; ni++)
            #pragma unroll
            for (int j = 0; j < 4; j++) acc[mi][ni][j] = 0.0f;

    // ldmatrix lane addressing (identical to the verified R2 layout)
    const int a_row  = warp_m * 64 + (lane & 15);
    const int a_half = lane >> 4;
    const int b_row  = warp_n * 32 + (lane & 7) + ((lane >> 4) << 3);
    const int b_half = (lane >> 3) & 1;

    #pragma unroll
    for (int j = 0; j < STAGES - 1; j++) load_stage(j, j);

    for (int it = 0; it < KT; it++) {
        const int st = it % STAGES;
        asm volatile("cp.async.wait_group %0;" :: "n"(STAGES - 2) : "memory");
        __syncthreads();

        const uint32_t abase = sb + st * STAGE_BYTES;
        const uint32_t bbase = abase + A_TILE_BYTES;

        #pragma unroll
        for (int ks = 0; ks < 4; ks++) {  // 4 x k16 covers BK=64
            uint32_t bfr[4][2];
            #pragma unroll
            for (int jt = 0; jt < 2; jt++) {
                const int n = b_row + jt * 16;
                const int ch = ks * 2 + b_half;
                uint32_t r4[4];
                ldsm_x4(r4, bbase + n * 128 + ((ch ^ (n & 7)) << 4));
                bfr[2 * jt + 0][0] = r4[0]; bfr[2 * jt + 0][1] = r4[1];
                bfr[2 * jt + 1][0] = r4[2]; bfr[2 * jt + 1][1] = r4[3];
            }
            #pragma unroll
            for (int mi = 0; mi < 4; mi++) {
                const int r = a_row + mi * 16;
                const int ch = ks * 2 + a_half;
                uint32_t a4[4];
                ldsm_x4(a4, abase + r * 128 + ((ch ^ (r & 7)) << 4));
                #pragma unroll
                for (int ni = 0; ni < 4; ni++)
                    mma16816(acc[mi][ni], a4, bfr[ni][0], bfr[ni][1]);
            }
        }

        if (it + STAGES - 1 < KT) load_stage(it + STAGES - 1, (it + STAGES - 1) % STAGES);
        else asm volatile("cp.async.commit_group;" ::: "memory");
    }

    // ---- epilogue: direct float2 stores ----
    const int er = lane >> 2;
    const int ec = (lane & 3) * 2;
    #pragma unroll
    for (int mi = 0; mi < 4; mi++) {
        #pragma unroll
        for (int ni = 0; ni < 4; ni++) {
            const int row = m0 + warp_m * 64 + mi * 16 + er;
            const int col = n0 + warp_n * 32 + ni * 8 + ec;
            float2 v0 = make_float2(acc[mi][ni][0], acc[mi][ni][1]);
            float2 v1 = make_float2(acc[mi][ni][2], acc[mi][ni][3]);
            *(float2*)&out[(size_t)row * N_DIM + col] = v0;
            *(float2*)&out[(size_t)(row + 8) * N_DIM + col] = v1;
        }
    }
}

// ---------------------------------------------------------------------------
// Launch
// ---------------------------------------------------------------------------
extern "C" void kernel_launch(void* const* d_in, const int* in_sizes, int n_in,
                              void* d_out, int out_size) {
    const float* x = (const float*)d_in[0];   // [8192, 4096]
    const float* w = (const float*)d_in[1];   // [4096, 4096]
    float* out = (float*)d_out;               // [8192, 4096]

    cudaFuncSetAttribute(k_gemm, cudaFuncAttributeMaxDynamicSharedMemorySize, SMEM_TOTAL);

    k_abs_partial<<<1024, 256>>>(w);
    k_thr<<<1, 1024>>>();
    k_quant<<<4096, 256>>>(w);
    k_conv<<<8192, 256>>>(x);

    // N-blocks fast: a concurrent wave shares q (32 MB, L2-resident)
    dim3 grid(N_DIM / BN, M_DIM / BM);
    k_gemm<<<grid, GEMM_THREADS, SMEM_TOTAL>>>(out);
}

// round 5
// speedup vs baseline: 5.4469x; 1.0361x over previous
#include <cuda_runtime.h>
#include <cuda_fp16.h>
#include <cstdint>
#include <cstddef>

// ---------------------------------------------------------------------------
// Problem dims
// ---------------------------------------------------------------------------
#define M_DIM 8192
#define N_DIM 4096
#define K_DIM 4096

// GEMM tiling
#define BM 128
#define BN 256
#define BK 64                    // fp16 elems per K-tile = 128 bytes/row
#define STAGES 3
#define KT (K_DIM / BK)          // 64
#define GEMM_THREADS 256         // 8 warps: 2 (M) x 4 (N), warp tile 64x64

#define A_TILE_BYTES (BM * 128)                    // 16 KB
#define B_TILE_BYTES (BN * 128)                    // 32 KB
#define STAGE_BYTES  (A_TILE_BYTES + B_TILE_BYTES) // 48 KB
#define SMEM_TOTAL   (STAGES * STAGE_BYTES)        // 144 KB

// ---------------------------------------------------------------------------
// Device scratch (allocation-free rule: __device__ globals)
// ---------------------------------------------------------------------------
__device__ float g_partials[1024];
__device__ float g_thr;
__device__ __align__(1024) __half g_q [(size_t)N_DIM * K_DIM]; // 32 MB {-1,0,1} exact
__device__ __align__(1024) __half g_xh[(size_t)M_DIM * K_DIM]; // 64 MB x in fp16

// ---------------------------------------------------------------------------
// Helpers
// ---------------------------------------------------------------------------
__device__ __forceinline__ uint32_t smem_u32(const void* p) {
    return (uint32_t)__cvta_generic_to_shared(p);
}

__device__ __forceinline__ void cp16(uint32_t dst, const void* src) {
    asm volatile("cp.async.cg.shared.global [%0], [%1], 16;" :: "r"(dst), "l"(src));
}

__device__ __forceinline__ void ldsm_x4(uint32_t (&r)[4], uint32_t addr) {
    asm volatile("ldmatrix.sync.aligned.m8n8.x4.shared.b16 {%0,%1,%2,%3}, [%4];"
                 : "=r"(r[0]), "=r"(r[1]), "=r"(r[2]), "=r"(r[3]) : "r"(addr));
}

__device__ __forceinline__ void mma16816(float (&c)[4], const uint32_t (&a)[4],
                                         uint32_t b0, uint32_t b1) {
    asm volatile(
        "mma.sync.aligned.m16n8k16.row.col.f32.f16.f16.f32 "
        "{%0,%1,%2,%3}, {%4,%5,%6,%7}, {%8,%9}, {%0,%1,%2,%3};"
        : "+f"(c[0]), "+f"(c[1]), "+f"(c[2]), "+f"(c[3])
        : "r"(a[0]), "r"(a[1]), "r"(a[2]), "r"(a[3]), "r"(b0), "r"(b1));
}

__device__ __forceinline__ uint32_t pack2h(float a, float b) {
    __half2 t = __floats2half2_rn(a, b);
    union { __half2 h; uint32_t u; } cv;
    cv.h = t;
    return cv.u;
}

// ---------------------------------------------------------------------------
// Prep kernels
// ---------------------------------------------------------------------------
__global__ void k_abs_partial(const float* __restrict__ w) {
    const float4* w4 = (const float4*)w;
    const int n4 = (N_DIM * K_DIM) / 4;
    float s = 0.0f;
    for (int i = blockIdx.x * blockDim.x + threadIdx.x; i < n4; i += gridDim.x * blockDim.x) {
        float4 v = w4[i];
        s += fabsf(v.x) + fabsf(v.y) + fabsf(v.z) + fabsf(v.w);
    }
    __shared__ float sm[256];
    sm[threadIdx.x] = s;
    __syncthreads();
    for (int o = 128; o > 0; o >>= 1) {
        if (threadIdx.x < o) sm[threadIdx.x] += sm[threadIdx.x + o];
        __syncthreads();
    }
    if (threadIdx.x == 0) g_partials[blockIdx.x] = sm[0];
}

__global__ void k_thr() {
    __shared__ float sm[1024];
    sm[threadIdx.x] = g_partials[threadIdx.x];
    __syncthreads();
    for (int o = 512; o > 0; o >>= 1) {
        if (threadIdx.x < o) sm[threadIdx.x] += sm[threadIdx.x + o];
        __syncthreads();
    }
    if (threadIdx.x == 0)
        g_thr = 0.05f * (sm[0] / (float)((size_t)N_DIM * K_DIM));
}

__device__ __forceinline__ float tq(float v, float thr) {
    return v > thr ? 1.0f : (v < -thr ? -1.0f : 0.0f);
}

// w -> ternary fp16 (exact)
__global__ void k_quant(const float* __restrict__ w) {
    const float thr = g_thr;
    const float4* w4 = (const float4*)w;
    uint2* q4 = (uint2*)g_q;
    const int n4 = (N_DIM * K_DIM) / 4;
    for (int i = blockIdx.x * blockDim.x + threadIdx.x; i < n4; i += gridDim.x * blockDim.x) {
        float4 v = w4[i];
        uint2 o;
        o.x = pack2h(tq(v.x, thr), tq(v.y, thr));
        o.y = pack2h(tq(v.z, thr), tq(v.w, thr));
        q4[i] = o;
    }
}

// x -> fp16
__global__ void k_conv(const float* __restrict__ x) {
    const float4* x4 = (const float4*)x;
    uint2* h4 = (uint2*)g_xh;
    const int n4 = (M_DIM * K_DIM) / 4;
    for (int i = blockIdx.x * blockDim.x + threadIdx.x; i < n4; i += gridDim.x * blockDim.x) {
        float4 v = x4[i];
        uint2 o;
        o.x = pack2h(v.x, v.y);
        o.y = pack2h(v.z, v.w);
        h4[i] = o;
    }
}

// ---------------------------------------------------------------------------
// GEMM: out = x_fp16 @ q^T via mma.sync m16n8k16 f16 (fp32 accum)
//   CTA tile 128x256, warp tile 64x64, 3-stage cp.async pipeline.
// ---------------------------------------------------------------------------
__global__ void __launch_bounds__(GEMM_THREADS, 1)
k_gemm(float* __restrict__ out) {
    extern __shared__ char smem[];
    const uint32_t sb = smem_u32(smem);
    const int tid  = threadIdx.x;
    const int wid  = tid >> 5;
    const int lane = tid & 31;
    const int warp_m = wid & 1;   // 64 rows each
    const int warp_n = wid >> 1;  // 64 cols each
    const int m0 = blockIdx.y * BM;
    const int n0 = blockIdx.x * BN;

    // ---- async tile loader (XOR-swizzled 16B chunks, 128B rows) ----
    auto load_stage = [&](int kt, int st) {
        const uint32_t base = sb + st * STAGE_BYTES;
        const size_t kofs = (size_t)kt * BK;
        #pragma unroll
        for (int i = tid; i < BM * 8; i += GEMM_THREADS) {
            const int r = i >> 3, c = i & 7;
            const uint32_t d = base + r * 128 + ((c ^ (r & 7)) << 4);
            cp16(d, &g_xh[(size_t)(m0 + r) * K_DIM + kofs + c * 8]);
        }
        #pragma unroll
        for (int i = tid; i < BN * 8; i += GEMM_THREADS) {
            const int r = i >> 3, c = i & 7;
            const uint32_t d = base + A_TILE_BYTES + r * 128 + ((c ^ (r & 7)) << 4);
            cp16(d, &g_q[(size_t)(n0 + r) * K_DIM + kofs + c * 8]);
        }
        asm volatile("cp.async.commit_group;" ::: "memory");
    };

    float acc[4][8][4];   // [mi][ni][frag] : 128 regs
    #pragma unroll
    for (int mi = 0; mi < 4; mi++)
        #pragma unroll
        for (int ni = 0; ni < 8; ni++)
            #pragma unroll
            for (int j = 0; j < 4; j++) acc[mi][ni][j] = 0.0f;

    // ldmatrix lane addressing (verified R2/R4 layout)
    const int a_row  = warp_m * 64 + (lane & 15);
    const int a_half = lane >> 4;
    const int b_row  = warp_n * 64 + (lane & 7) + ((lane >> 4) << 3);
    const int b_half = (lane >> 3) & 1;

    #pragma unroll
    for (int j = 0; j < STAGES - 1; j++) load_stage(j, j);

    for (int it = 0; it < KT; it++) {
        const int st = it % STAGES;
        asm volatile("cp.async.wait_group %0;" :: "n"(STAGES - 2) : "memory");
        __syncthreads();

        const uint32_t abase = sb + st * STAGE_BYTES;
        const uint32_t bbase = abase + A_TILE_BYTES;

        #pragma unroll
        for (int ks = 0; ks < 4; ks++) {  // 4 x k16 covers BK=64
            // B frags: 4 ldsm.x4 -> 8 n8-frags
            uint32_t bfr[8][2];
            #pragma unroll
            for (int jt = 0; jt < 4; jt++) {
                const int n = b_row + jt * 16;
                const int ch = ks * 2 + b_half;
                uint32_t r4[4];
                ldsm_x4(r4, bbase + n * 128 + ((ch ^ (n & 7)) << 4));
                bfr[2 * jt + 0][0] = r4[0]; bfr[2 * jt + 0][1] = r4[1];
                bfr[2 * jt + 1][0] = r4[2]; bfr[2 * jt + 1][1] = r4[3];
            }
            // A frags + MMA
            #pragma unroll
            for (int mi = 0; mi < 4; mi++) {
                const int r = a_row + mi * 16;
                const int ch = ks * 2 + a_half;
                uint32_t a4[4];
                ldsm_x4(a4, abase + r * 128 + ((ch ^ (r & 7)) << 4));
                #pragma unroll
                for (int ni = 0; ni < 8; ni++)
                    mma16816(acc[mi][ni], a4, bfr[ni][0], bfr[ni][1]);
            }
        }

        if (it + STAGES - 1 < KT) load_stage(it + STAGES - 1, (it + STAGES - 1) % STAGES);
        else asm volatile("cp.async.commit_group;" ::: "memory");
    }

    // ---- epilogue: direct float2 stores ----
    const int er = lane >> 2;
    const int ec = (lane & 3) * 2;
    #pragma unroll
    for (int mi = 0; mi < 4; mi++) {
        #pragma unroll
        for (int ni = 0; ni < 8; ni++) {
            const int row = m0 + warp_m * 64 + mi * 16 + er;
            const int col = n0 + warp_n * 64 + ni * 8 + ec;
            float2 v0 = make_float2(acc[mi][ni][0], acc[mi][ni][1]);
            float2 v1 = make_float2(acc[mi][ni][2], acc[mi][ni][3]);
            *(float2*)&out[(size_t)row * N_DIM + col] = v0;
            *(float2*)&out[(size_t)(row + 8) * N_DIM + col] = v1;
        }
    }
}

// ---------------------------------------------------------------------------
// Launch
// ---------------------------------------------------------------------------
extern "C" void kernel_launch(void* const* d_in, const int* in_sizes, int n_in,
                              void* d_out, int out_size) {
    const float* x = (const float*)d_in[0];   // [8192, 4096]
    const float* w = (const float*)d_in[1];   // [4096, 4096]
    float* out = (float*)d_out;               // [8192, 4096]

    cudaFuncSetAttribute(k_gemm, cudaFuncAttributeMaxDynamicSharedMemorySize, SMEM_TOTAL);

    k_abs_partial<<<1024, 256>>>(w);
    k_thr<<<1, 1024>>>();
    k_quant<<<4096, 256>>>(w);
    k_conv<<<8192, 256>>>(x);

    // N-blocks fast: a concurrent wave shares q (32 MB, L2-resident)
    dim3 grid(N_DIM / BN, M_DIM / BM);
    k_gemm<<<grid, GEMM_THREADS, SMEM_TOTAL>>>(out);
}

// round 6
// speedup vs baseline: 5.6171x; 1.0312x over previous
#include <cuda_runtime.h>
#include <cuda_fp16.h>
#include <cstdint>
#include <cstddef>

// ---------------------------------------------------------------------------
// Problem dims
// ---------------------------------------------------------------------------
#define M_DIM 8192
#define N_DIM 4096
#define K_DIM 4096

// GEMM tiling
#define BM 128
#define BN 256
#define BK 64                    // fp16 elems per K-tile = 128 bytes/row
#define STAGES 4
#define KT (K_DIM / BK)          // 64
#define GEMM_THREADS 256         // 8 warps: 2 (M) x 4 (N), warp tile 64x64

#define A_TILE_BYTES (BM * 128)                    // 16 KB
#define B_TILE_BYTES (BN * 128)                    // 32 KB
#define STAGE_BYTES  (A_TILE_BYTES + B_TILE_BYTES) // 48 KB
#define SMEM_TOTAL   (STAGES * STAGE_BYTES)        // 192 KB

#define PREP_CONV_BLOCKS 8192
#define PREP_ABS_BLOCKS  1024

// ---------------------------------------------------------------------------
// Device scratch (allocation-free rule: __device__ globals)
// ---------------------------------------------------------------------------
__device__ float g_partials[PREP_ABS_BLOCKS];
__device__ __align__(1024) __half g_q [(size_t)N_DIM * K_DIM]; // 32 MB {-1,0,1} exact
__device__ __align__(1024) __half g_xh[(size_t)M_DIM * K_DIM]; // 64 MB x in fp16

// ---------------------------------------------------------------------------
// Helpers
// ---------------------------------------------------------------------------
__device__ __forceinline__ uint32_t smem_u32(const void* p) {
    return (uint32_t)__cvta_generic_to_shared(p);
}

__device__ __forceinline__ void cp16(uint32_t dst, const void* src) {
    asm volatile("cp.async.cg.shared.global [%0], [%1], 16;" :: "r"(dst), "l"(src));
}

__device__ __forceinline__ void ldsm_x4(uint32_t (&r)[4], uint32_t addr) {
    asm volatile("ldmatrix.sync.aligned.m8n8.x4.shared.b16 {%0,%1,%2,%3}, [%4];"
                 : "=r"(r[0]), "=r"(r[1]), "=r"(r[2]), "=r"(r[3]) : "r"(addr));
}

__device__ __forceinline__ void mma16816(float (&c)[4], const uint32_t (&a)[4],
                                         uint32_t b0, uint32_t b1) {
    asm volatile(
        "mma.sync.aligned.m16n8k16.row.col.f32.f16.f16.f32 "
        "{%0,%1,%2,%3}, {%4,%5,%6,%7}, {%8,%9}, {%0,%1,%2,%3};"
        : "+f"(c[0]), "+f"(c[1]), "+f"(c[2]), "+f"(c[3])
        : "r"(a[0]), "r"(a[1]), "r"(a[2]), "r"(a[3]), "r"(b0), "r"(b1));
}

__device__ __forceinline__ uint32_t pack2h(float a, float b) {
    __half2 t = __floats2half2_rn(a, b);
    union { __half2 h; uint32_t u; } cv;
    cv.h = t;
    return cv.u;
}

// ---------------------------------------------------------------------------
// Prep 1: fused x->fp16 conversion (blocks 0..8191) + |w| partial sums
//         (blocks 8192..9215)
// ---------------------------------------------------------------------------
__global__ void k_prep(const float* __restrict__ x, const float* __restrict__ w) {
    if (blockIdx.x < PREP_CONV_BLOCKS) {
        const float4* x4 = (const float4*)x;
        uint2* h4 = (uint2*)g_xh;
        const int n4 = (M_DIM * K_DIM) / 4;
        for (int i = blockIdx.x * blockDim.x + threadIdx.x; i < n4;
             i += PREP_CONV_BLOCKS * blockDim.x) {
            float4 v = x4[i];
            uint2 o;
            o.x = pack2h(v.x, v.y);
            o.y = pack2h(v.z, v.w);
            h4[i] = o;
        }
    } else {
        const int bid = blockIdx.x - PREP_CONV_BLOCKS;
        const float4* w4 = (const float4*)w;
        const int n4 = (N_DIM * K_DIM) / 4;
        float s = 0.0f;
        for (int i = bid * blockDim.x + threadIdx.x; i < n4;
             i += PREP_ABS_BLOCKS * blockDim.x) {
            float4 v = w4[i];
            s += fabsf(v.x) + fabsf(v.y) + fabsf(v.z) + fabsf(v.w);
        }
        __shared__ float sm[256];
        sm[threadIdx.x] = s;
        __syncthreads();
        for (int o = 128; o > 0; o >>= 1) {
            if (threadIdx.x < o) sm[threadIdx.x] += sm[threadIdx.x + o];
            __syncthreads();
        }
        if (threadIdx.x == 0) g_partials[bid] = sm[0];
    }
}

// ---------------------------------------------------------------------------
// Prep 2: each block re-reduces the 1024 partials (deterministic fixed-order
// tree, identical in every block) then ternary-quantizes w -> fp16 {-1,0,1}
// ---------------------------------------------------------------------------
__global__ void k_quant(const float* __restrict__ w) {
    __shared__ float sm[256];
    // fixed-order reduction of g_partials: each thread sums 4 in index order
    {
        float s = 0.0f;
        #pragma unroll
        for (int j = 0; j < 4; j++) s += g_partials[threadIdx.x * 4 + j];
        sm[threadIdx.x] = s;
        __syncthreads();
        for (int o = 128; o > 0; o >>= 1) {
            if (threadIdx.x < o) sm[threadIdx.x] += sm[threadIdx.x + o];
            __syncthreads();
        }
    }
    const float thr = 0.05f * (sm[0] / (float)((size_t)N_DIM * K_DIM));

    const float4* w4 = (const float4*)w;
    uint2* q4 = (uint2*)g_q;
    const int n4 = (N_DIM * K_DIM) / 4;
    auto tq = [&](float v) -> float {
        return v > thr ? 1.0f : (v < -thr ? -1.0f : 0.0f);
    };
    for (int i = blockIdx.x * blockDim.x + threadIdx.x; i < n4;
         i += gridDim.x * blockDim.x) {
        float4 v = w4[i];
        uint2 o;
        o.x = pack2h(tq(v.x), tq(v.y));
        o.y = pack2h(tq(v.z), tq(v.w));
        q4[i] = o;
    }
}

// ---------------------------------------------------------------------------
// GEMM: out = x_fp16 @ q^T via mma.sync m16n8k16 f16 (fp32 accum)
//   CTA tile 128x256, warp tile 64x64, 4-stage cp.async pipeline.
// ---------------------------------------------------------------------------
__global__ void __launch_bounds__(GEMM_THREADS, 1)
k_gemm(float* __restrict__ out) {
    extern __shared__ char smem[];
    const uint32_t sb = smem_u32(smem);
    const int tid  = threadIdx.x;
    const int wid  = tid >> 5;
    const int lane = tid & 31;
    const int warp_m = wid & 1;   // 64 rows each
    const int warp_n = wid >> 1;  // 64 cols each
    const int m0 = blockIdx.y * BM;
    const int n0 = blockIdx.x * BN;

    // ---- async tile loader (XOR-swizzled 16B chunks, 128B rows) ----
    auto load_stage = [&](int kt, int st) {
        const uint32_t base = sb + st * STAGE_BYTES;
        const size_t kofs = (size_t)kt * BK;
        #pragma unroll
        for (int i = tid; i < BM * 8; i += GEMM_THREADS) {
            const int r = i >> 3, c = i & 7;
            const uint32_t d = base + r * 128 + ((c ^ (r & 7)) << 4);
            cp16(d, &g_xh[(size_t)(m0 + r) * K_DIM + kofs + c * 8]);
        }
        #pragma unroll
        for (int i = tid; i < BN * 8; i += GEMM_THREADS) {
            const int r = i >> 3, c = i & 7;
            const uint32_t d = base + A_TILE_BYTES + r * 128 + ((c ^ (r & 7)) << 4);
            cp16(d, &g_q[(size_t)(n0 + r) * K_DIM + kofs + c * 8]);
        }
        asm volatile("cp.async.commit_group;" ::: "memory");
    };

    float acc[4][8][4];   // [mi][ni][frag] : 128 regs
    #pragma unroll
    for (int mi = 0; mi < 4; mi++)
        #pragma unroll
        for (int ni = 0; ni < 8; ni++)
            #pragma unroll
            for (int j = 0; j < 4; j++) acc[mi][ni][j] = 0.0f;

    // ldmatrix lane addressing (verified R2/R4/R5 layout)
    const int a_row  = warp_m * 64 + (lane & 15);
    const int a_half = lane >> 4;
    const int b_row  = warp_n * 64 + (lane & 7) + ((lane >> 4) << 3);
    const int b_half = (lane >> 3) & 1;

    #pragma unroll
    for (int j = 0; j < STAGES - 1; j++) load_stage(j, j);

    for (int it = 0; it < KT; it++) {
        const int st = it % STAGES;
        asm volatile("cp.async.wait_group %0;" :: "n"(STAGES - 2) : "memory");
        __syncthreads();

        const uint32_t abase = sb + st * STAGE_BYTES;
        const uint32_t bbase = abase + A_TILE_BYTES;

        #pragma unroll
        for (int ks = 0; ks < 4; ks++) {  // 4 x k16 covers BK=64
            // B frags: 4 ldsm.x4 -> 8 n8-frags
            uint32_t bfr[8][2];
            #pragma unroll
            for (int jt = 0; jt < 4; jt++) {
                const int n = b_row + jt * 16;
                const int ch = ks * 2 + b_half;
                uint32_t r4[4];
                ldsm_x4(r4, bbase + n * 128 + ((ch ^ (n & 7)) << 4));
                bfr[2 * jt + 0][0] = r4[0]; bfr[2 * jt + 0][1] = r4[1];
                bfr[2 * jt + 1][0] = r4[2]; bfr[2 * jt + 1][1] = r4[3];
            }
            // A frags + MMA
            #pragma unroll
            for (int mi = 0; mi < 4; mi++) {
                const int r = a_row + mi * 16;
                const int ch = ks * 2 + a_half;
                uint32_t a4[4];
                ldsm_x4(a4, abase + r * 128 + ((ch ^ (r & 7)) << 4));
                #pragma unroll
                for (int ni = 0; ni < 8; ni++)
                    mma16816(acc[mi][ni], a4, bfr[ni][0], bfr[ni][1]);
            }
        }

        if (it + STAGES - 1 < KT) load_stage(it + STAGES - 1, (it + STAGES - 1) % STAGES);
        else asm volatile("cp.async.commit_group;" ::: "memory");
    }

    // ---- epilogue: direct float2 stores ----
    const int er = lane >> 2;
    const int ec = (lane & 3) * 2;
    #pragma unroll
    for (int mi = 0; mi < 4; mi++) {
        #pragma unroll
        for (int ni = 0; ni < 8; ni++) {
            const int row = m0 + warp_m * 64 + mi * 16 + er;
            const int col = n0 + warp_n * 64 + ni * 8 + ec;
            float2 v0 = make_float2(acc[mi][ni][0], acc[mi][ni][1]);
            float2 v1 = make_float2(acc[mi][ni][2], acc[mi][ni][3]);
            *(float2*)&out[(size_t)row * N_DIM + col] = v0;
            *(float2*)&out[(size_t)(row + 8) * N_DIM + col] = v1;
        }
    }
}

// ---------------------------------------------------------------------------
// Launch
// ---------------------------------------------------------------------------
extern "C" void kernel_launch(void* const* d_in, const int* in_sizes, int n_in,
                              void* d_out, int out_size) {
    const float* x = (const float*)d_in[0];   // [8192, 4096]
    const float* w = (const float*)d_in[1];   // [4096, 4096]
    float* out = (float*)d_out;               // [8192, 4096]

    cudaFuncSetAttribute(k_gemm, cudaFuncAttributeMaxDynamicSharedMemorySize, SMEM_TOTAL);

    k_prep<<<PREP_CONV_BLOCKS + PREP_ABS_BLOCKS, 256>>>(x, w);
    k_quant<<<4096, 256>>>(w);

    // N-blocks fast: a concurrent wave shares q (32 MB, L2-resident)
    dim3 grid(N_DIM / BN, M_DIM / BM);
    k_gemm<<<grid, GEMM_THREADS, SMEM_TOTAL>>>(out);
}